// round 1
// baseline (speedup 1.0000x reference)
#include <cuda_runtime.h>

// VDEmbedding: out[t, :] = mask[x[t]] * weight[x[t], :], zero at pad (idx==0).
// x: [65536] int64 OR int32 (JAX x64-dependent) -> auto-detected on device.
// weight: [128000, 128] f32, mask: [128000] f32, out: [65536, 128] f32.

#define EMBED_V4 32   // 128 floats = 32 float4 per row

// 1 == indices are int32, 0 == indices are int64. Recomputed every launch
// (deterministic: pure function of the input buffer).
__device__ int g_idx_is_i32;

// If x is int64 (values < 128000, non-negative), every odd 32-bit word is 0.
// If x is int32, odd words are random token ids in [0,128000): P(all 2048
// sampled words == 0) ~ (1/128000)^2048 ~ 0. Reads stay within the first
// 16 KB, valid for both layouts (int32 buffer is 256 KB).
__global__ void detect_idx_dtype_kernel(const unsigned int* __restrict__ xw) {
    __shared__ int s_any;
    if (threadIdx.x == 0) s_any = 0;
    __syncthreads();
    unsigned int acc = 0;
    for (int i = threadIdx.x; i < 2048; i += blockDim.x)
        acc |= xw[2 * i + 1];
    if (acc) s_any = 1;
    __syncthreads();
    if (threadIdx.x == 0) g_idx_is_i32 = s_any;
}

__global__ __launch_bounds__(256) void vdembed_kernel(
    const void*   __restrict__ xraw,
    const float4* __restrict__ w4,     // weight viewed as [V, 32] float4
    const float*  __restrict__ mask,
    float4*       __restrict__ out4,   // out viewed as [T, 32] float4
    int n_tokens)
{
    const int warp = (int)((blockIdx.x * blockDim.x + threadIdx.x) >> 5);
    const int lane = threadIdx.x & 31;
    if (warp >= n_tokens) return;

    long long idx;
    if (g_idx_is_i32) idx = (long long)((const int*)xraw)[warp];
    else              idx = ((const long long*)xraw)[warp];

    const float scale = (idx == 0) ? 0.0f : __ldg(&mask[idx]);

    float4 v = __ldg(&w4[idx * EMBED_V4 + lane]);
    v.x *= scale; v.y *= scale; v.z *= scale; v.w *= scale;

    out4[(long long)warp * EMBED_V4 + lane] = v;
}

extern "C" void kernel_launch(void* const* d_in, const int* in_sizes, int n_in,
                              void* d_out, int out_size) {
    const void*  x    = d_in[0];                       // [B*S] int64 or int32
    const float* w    = (const float*)d_in[1];         // [V, 128]
    const float* mask = (const float*)d_in[2];         // [V]
    float*       out  = (float*)d_out;                 // [B*S, 128]

    const int n_tokens = in_sizes[0];

    detect_idx_dtype_kernel<<<1, 256>>>((const unsigned int*)x);

    // one warp per token, 8 warps per block
    const int threads = 256;
    const int blocks  = (n_tokens * 32 + threads - 1) / threads;
    vdembed_kernel<<<blocks, threads>>>(
        x, (const float4*)w, mask, (float4*)out, n_tokens);
}

// round 2
// speedup vs baseline: 1.1579x; 1.1579x over previous
#include <cuda_runtime.h>

// VDEmbedding: out[t, :] = mask[x[t]] * weight[x[t], :], zero at pad (idx==0).
// x: [65536] int64 OR int32 (auto-detected), weight: [128000,128] f32,
// mask: [128000] f32, out: [65536,128] f32.
//
// R2: 4 tokens per warp (MLP 1 -> 4 on the gather chain) + streaming output
// stores (__stcs) so the weight table stays resident in L2.

#define EMBED_V4 32   // 128 floats = 32 float4 per row
#define TOK_PER_WARP 4

__device__ int g_idx_is_i32;

// If x is int64 (values < 128000), every odd 32-bit word is 0. If int32,
// odd words are random token ids -> almost surely nonzero in 2048 samples.
__global__ void detect_idx_dtype_kernel(const unsigned int* __restrict__ xw) {
    __shared__ int s_any;
    if (threadIdx.x == 0) s_any = 0;
    __syncthreads();
    unsigned int acc = 0;
    for (int i = threadIdx.x; i < 2048; i += blockDim.x)
        acc |= xw[2 * i + 1];
    if (acc) s_any = 1;
    __syncthreads();
    if (threadIdx.x == 0) g_idx_is_i32 = s_any;
}

__global__ __launch_bounds__(256) void vdembed_kernel(
    const void*   __restrict__ xraw,
    const float4* __restrict__ w4,     // weight as [V, 32] float4
    const float*  __restrict__ mask,
    float4*       __restrict__ out4,   // out as [T, 32] float4
    int n_tokens)
{
    const int warp = (int)((blockIdx.x * blockDim.x + threadIdx.x) >> 5);
    const int lane = threadIdx.x & 31;
    const int t0   = warp * TOK_PER_WARP;
    if (t0 >= n_tokens) return;

    // ---- batch 1: indices (uniform across warp; L1 broadcast) ----
    long long i0, i1, i2, i3;
    if (g_idx_is_i32) {
        const int* xi = (const int*)xraw;
        i0 = xi[t0]; i1 = xi[t0 + 1]; i2 = xi[t0 + 2]; i3 = xi[t0 + 3];
    } else {
        const long long* xl = (const long long*)xraw;
        i0 = xl[t0]; i1 = xl[t0 + 1]; i2 = xl[t0 + 2]; i3 = xl[t0 + 3];
    }

    // ---- batch 2: 4 independent mask loads + 4 independent row gathers ----
    const float s0 = (i0 == 0) ? 0.0f : __ldg(&mask[i0]);
    const float s1 = (i1 == 0) ? 0.0f : __ldg(&mask[i1]);
    const float s2 = (i2 == 0) ? 0.0f : __ldg(&mask[i2]);
    const float s3 = (i3 == 0) ? 0.0f : __ldg(&mask[i3]);

    float4 v0 = __ldg(&w4[i0 * EMBED_V4 + lane]);
    float4 v1 = __ldg(&w4[i1 * EMBED_V4 + lane]);
    float4 v2 = __ldg(&w4[i2 * EMBED_V4 + lane]);
    float4 v3 = __ldg(&w4[i3 * EMBED_V4 + lane]);

    v0.x *= s0; v0.y *= s0; v0.z *= s0; v0.w *= s0;
    v1.x *= s1; v1.y *= s1; v1.z *= s1; v1.w *= s1;
    v2.x *= s2; v2.y *= s2; v2.z *= s2; v2.w *= s2;
    v3.x *= s3; v3.y *= s3; v3.z *= s3; v3.w *= s3;

    // ---- batch 3: streaming stores (no L2 reuse for output) ----
    float4* o = out4 + (long long)t0 * EMBED_V4 + lane;
    __stcs(o + 0 * EMBED_V4, v0);
    __stcs(o + 1 * EMBED_V4, v1);
    __stcs(o + 2 * EMBED_V4, v2);
    __stcs(o + 3 * EMBED_V4, v3);
}

extern "C" void kernel_launch(void* const* d_in, const int* in_sizes, int n_in,
                              void* d_out, int out_size) {
    const void*  x    = d_in[0];                 // [B*S] int64 or int32
    const float* w    = (const float*)d_in[1];   // [V, 128]
    const float* mask = (const float*)d_in[2];   // [V]
    float*       out  = (float*)d_out;           // [B*S, 128]

    const int n_tokens = in_sizes[0];

    detect_idx_dtype_kernel<<<1, 256>>>((const unsigned int*)x);

    const int warps   = (n_tokens + TOK_PER_WARP - 1) / TOK_PER_WARP;
    const int threads = 256;
    const int blocks  = (warps * 32 + threads - 1) / threads;
    vdembed_kernel<<<blocks, threads>>>(
        x, (const float4*)w, mask, (float4*)out, n_tokens);
}